// round 9
// baseline (speedup 1.0000x reference)
#include <cuda_runtime.h>
#include <cuda_fp16.h>
#include <cstdint>
#include <math.h>

#define NB    1024
#define ND    256
#define NV    50000
#define NC    64
#define NTOPK 10

#define KPRIME 768            // 3 * ND virtual K (fp16 2-split, 3 products)
#define BM 128
#define BN 128
#define BKE 64                // fp16 elements per k-chunk (128 B rows)
#define NKIT (KPRIME / BKE)   // 12
#define NTN 392               // n-tiles (50176 / 128)
#define NPADN (NTN * BN)      // 50176
#define NTILES (8 * NTN)      // 3136 total tiles

// ---------------- scratch (device globals) ----------------------------------
__device__ __align__(16) float g_words [2048 * ND];
__device__ __align__(16) float g_align [2048 * ND];
__device__ __align__(16) float g_concat[NB * 2 * ND];
__device__ __align__(16) __half g_Ah[(size_t)NB * KPRIME];      // 1.5 MB
__device__ __align__(16) __half g_Bh[(size_t)NPADN * KPRIME];   // 77 MB
__device__ float g_smax[(size_t)NTN * NB];
__device__ float g_ssum[(size_t)NTN * NB];

// ---------------- helpers -----------------------------------------------------
__device__ __forceinline__ uint32_t swz(uint32_t b) { return b ^ ((b >> 3) & 0x70); }

__device__ __forceinline__ void fma_f32x2(unsigned long long &d,
                                          unsigned long long a,
                                          unsigned long long b) {
    asm("fma.rn.f32x2 %0, %1, %2, %0;" : "+l"(d) : "l"(a), "l"(b));
}
__device__ __forceinline__ unsigned long long dup_f32(float a) {
    unsigned int u = __float_as_uint(a);
    unsigned long long r;
    asm("mov.b64 %0, {%1, %1};" : "=l"(r) : "r"(u));
    return r;
}
__device__ __forceinline__ float2 unpack_f32x2(unsigned long long v) {
    float2 f;
    f.x = __uint_as_float((unsigned int)(v & 0xffffffffull));
    f.y = __uint_as_float((unsigned int)(v >> 32));
    return f;
}
__device__ __forceinline__ uint32_t cvta_smem(const void* p) {
    uint32_t a;
    asm("{ .reg .u64 t; cvta.to.shared.u64 t, %1; cvt.u32.u64 %0, t; }"
        : "=r"(a) : "l"(p));
    return a;
}
__device__ __forceinline__ void cpa16(uint32_t d, const void* s) {
    asm volatile("cp.async.cg.shared.global [%0], [%1], 16;" :: "r"(d), "l"(s));
}
#define CP_COMMIT() asm volatile("cp.async.commit_group;" ::: "memory")
#define CP_WAIT1()  asm volatile("cp.async.wait_group 1;" ::: "memory")

#define LDMX4(r, a) \
    asm volatile("ldmatrix.sync.aligned.m8n8.x4.shared.b16 {%0,%1,%2,%3}, [%4];" \
        : "=r"((r)[0]), "=r"((r)[1]), "=r"((r)[2]), "=r"((r)[3]) : "r"(a))

#define MMA16816(c, a, b0, b1) \
    asm volatile("mma.sync.aligned.m16n8k16.row.col.f32.f16.f16.f32 " \
        "{%0,%1,%2,%3}, {%4,%5,%6,%7}, {%8,%9}, {%0,%1,%2,%3};" \
        : "+f"((c)[0]), "+f"((c)[1]), "+f"((c)[2]), "+f"((c)[3]) \
        : "r"((a)[0]), "r"((a)[1]), "r"((a)[2]), "r"((a)[3]), "r"(b0), "r"(b1))

// ---------------- fp16 2-split helpers ------------------------------------------
__device__ __forceinline__ void split2(float x, float& h, float& l) {
    __half hh = __float2half_rn(x);
    h = __half2float(hh);
    l = x - h;
}
__device__ __forceinline__ __half2 mkh2(float a, float b) {
    return __halves2half2(__float2half_rn(a), __float2half_rn(b));
}

// ---------------- prep: fused gather_words + convB ------------------------------
__global__ void k_prep(const int* __restrict__ wl,
                       const int* __restrict__ wr,
                       const float* __restrict__ wemb,
                       const float* __restrict__ cemb) {
    if (blockIdx.x < 512) {
        int idx = blockIdx.x * 256 + threadIdx.x;
        int r = idx >> 6, q = idx & 63;
        int id = (r < NB) ? wl[r] : wr[r - NB];
        const float4* src = reinterpret_cast<const float4*>(wemb);
        float4* dst = reinterpret_cast<float4*>(g_words);
        dst[(size_t)r * 64 + q] = src[(size_t)id * 64 + q];
        return;
    }
    size_t tid = (size_t)(blockIdx.x - 512) * 256 + threadIdx.x;  // 50000*128 total
    int n = (int)(tid >> 7);
    int k = (int)(tid & 127) * 2;
    float2 v = *reinterpret_cast<const float2*>(cemb + (size_t)n * ND + k);
    float h0, l0, h1, l1;
    split2(v.x, h0, l0);
    split2(v.y, h1, l1);
    __half2* row = reinterpret_cast<__half2*>(g_Bh + (size_t)n * KPRIME);
    row[k / 2]         = mkh2(h0, h1);                       // b0
    row[(256 + k) / 2] = mkh2(l0 * 32.f, l1 * 32.f);         // b1*32
    row[(512 + k) / 2] = mkh2(h0 * 0.03125f, h1 * 0.03125f); // b0/32
}

// ---------------- fp32 64x64-tile GEMM; SPLIT_OUT=1 writes fp16 split A' --------
template<int SPLIT_OUT>
__global__ void k_gemm_small64(const float* __restrict__ A, const float* __restrict__ Bm,
                               const float* __restrict__ bias, float* __restrict__ Cc,
                               int M, int N, int K) {
    const int TBK = 16;
    __shared__ __align__(16) float As[TBK][64];
    __shared__ __align__(16) float Bs[TBK][64];
    int tid = threadIdx.x;          // 128 threads
    int tx = tid & 7, ty = tid >> 3;
    int m0 = blockIdx.y * 64;
    int n0 = blockIdx.x * 64;

    unsigned long long acc[4][4];
    #pragma unroll
    for (int i = 0; i < 4; i++)
        #pragma unroll
        for (int j = 0; j < 4; j++) acc[i][j] = 0ull;

    for (int k0 = 0; k0 < K; k0 += TBK) {
        #pragma unroll
        for (int p = 0; p < 2; p++) {
            int f = tid + p * 128;
            int row = f >> 2, kv = f & 3;
            float4 v = *reinterpret_cast<const float4*>(
                A + (size_t)(m0 + row) * K + k0 + kv * 4);
            As[kv * 4 + 0][row] = v.x;
            As[kv * 4 + 1][row] = v.y;
            As[kv * 4 + 2][row] = v.z;
            As[kv * 4 + 3][row] = v.w;
        }
        #pragma unroll
        for (int p = 0; p < 2; p++) {
            int f = tid + p * 128;
            int kk = f >> 4, nv = f & 15;
            float4 v = *reinterpret_cast<const float4*>(
                Bm + (size_t)(k0 + kk) * N + n0 + nv * 4);
            *reinterpret_cast<float4*>(&Bs[kk][nv * 4]) = v;
        }
        __syncthreads();

        #pragma unroll
        for (int k = 0; k < TBK; k++) {
            float af[4];
            *reinterpret_cast<float4*>(af) =
                *reinterpret_cast<const float4*>(&As[k][ty * 4]);
            const ulonglong2* bp = reinterpret_cast<const ulonglong2*>(&Bs[k][tx * 8]);
            ulonglong2 b01 = bp[0], b23 = bp[1];
            unsigned long long bf[4] = {b01.x, b01.y, b23.x, b23.y};
            #pragma unroll
            for (int i = 0; i < 4; i++) {
                unsigned long long ad = dup_f32(af[i]);
                #pragma unroll
                for (int j = 0; j < 4; j++) fma_f32x2(acc[i][j], ad, bf[j]);
            }
        }
        __syncthreads();
    }

    #pragma unroll
    for (int i = 0; i < 4; i++) {
        int m = m0 + ty * 4 + i;
        #pragma unroll
        for (int j = 0; j < 4; j++) {
            int n = n0 + tx * 8 + j * 2;
            float2 r = unpack_f32x2(acc[i][j]);
            r.x = tanhf(r.x + bias[n]);
            r.y = tanhf(r.y + bias[n + 1]);
            if (SPLIT_OUT) {
                float h0, l0, h1, l1;
                split2(r.x, h0, l0);
                split2(r.y, h1, l1);
                __half2* row = reinterpret_cast<__half2*>(g_Ah + (size_t)m * KPRIME);
                row[n / 2]         = mkh2(h0, h1);
                row[(256 + n) / 2] = mkh2(h0 * 0.03125f, h1 * 0.03125f);
                row[(512 + n) / 2] = mkh2(l0 * 32.f, l1 * 32.f);
            } else {
                *reinterpret_cast<float2*>(Cc + (size_t)m * N + n) = r;
            }
        }
    }
}

// ---------------- fused attention (both sides) + concat -------------------------
__global__ void k_attend2(const int* __restrict__ cand_l,
                          const int* __restrict__ cand_r,
                          const float* __restrict__ cemb) {
    int b = blockIdx.x;
    int t = threadIdx.x, w = t >> 5, l = t & 31;

    __shared__ float al[2][ND];
    __shared__ int ids_sm[2][NC];
    __shared__ float sc[2][NC];
    __shared__ float att[2][NC];

    al[0][t] = g_align[(size_t)b * ND + t];
    al[1][t] = g_align[(size_t)(NB + b) * ND + t];
    if (t < NC)            ids_sm[0][t]      = cand_r[b * NC + t];       // side 0
    else if (t < 2 * NC)   ids_sm[1][t - NC] = cand_l[b * NC + (t - NC)]; // side 1
    __syncthreads();

    // scores: warp w handles candidates w*8..w*8+7, both sides
    #pragma unroll
    for (int side = 0; side < 2; side++) {
        #pragma unroll
        for (int ci = 0; ci < 8; ci++) {
            int c = w * 8 + ci;
            const float* e = cemb + (size_t)ids_sm[side][c] * ND;
            float p = 0.f;
            #pragma unroll
            for (int j = 0; j < 8; j++) {
                int d = l + 32 * j;
                p += e[d] * al[side][d];
            }
            #pragma unroll
            for (int o = 16; o > 0; o >>= 1) p += __shfl_down_sync(0xffffffffu, p, o);
            if (l == 0) sc[side][c] = p;
        }
    }
    __syncthreads();

    // softmax over 64: warp 0 -> side 0, warp 1 -> side 1
    if (t < 64) {
        int side = w;
        float s0 = sc[side][l], s1 = sc[side][l + 32];
        float mx = fmaxf(s0, s1);
        #pragma unroll
        for (int o = 16; o > 0; o >>= 1) mx = fmaxf(mx, __shfl_xor_sync(0xffffffffu, mx, o));
        float e0 = expf(s0 - mx), e1 = expf(s1 - mx);
        float sum = e0 + e1;
        #pragma unroll
        for (int o = 16; o > 0; o >>= 1) sum += __shfl_xor_sync(0xffffffffu, sum, o);
        att[side][l] = e0 / sum;
        att[side][l + 32] = e1 / sum;
    }
    __syncthreads();

    // weighted sums (both sides) + concat
    float a0 = 0.f, a1 = 0.f;
    #pragma unroll 8
    for (int c = 0; c < NC; c++) {
        a0 += att[0][c] * __ldg(cemb + (size_t)ids_sm[0][c] * ND + t);
        a1 += att[1][c] * __ldg(cemb + (size_t)ids_sm[1][c] * ND + t);
    }
    float wsum = g_words[(size_t)b * ND + t] + g_words[(size_t)(NB + b) * ND + t];
    g_concat[(size_t)b * 2 * ND + t]       = wsum;
    g_concat[(size_t)b * 2 * ND + ND + t]  = a0 + a1;
}

// ---------------- persistent HMMA fp16 split GEMM + fused softmax stats ---------
// grid = 2*num_SMs, 256 threads, BM=128 BN=128, warp tile 32x64, continuous
// 3-stage cp.async ring across tile boundaries. Stats scratch past the stages.
#define STAGE_BYTES 32768     // A 16KB + B 16KB
#define NSTAGE 3
#define STATS_BYTES 2560      // rmaxs 256f + rsums 256f + segm 128f
#define SMEM_DYN (NSTAGE * STAGE_BYTES + STATS_BYTES)
__global__ void __launch_bounds__(256, 2) k_gemm_hmma(float* __restrict__ out) {
    extern __shared__ __align__(128) char smraw[];
    uint32_t sb = cvta_smem(smraw);
    int tid = threadIdx.x, wid = tid >> 5, lane = tid & 31;
    int wm = (wid & 3) * 32;
    int wn = (wid >> 2) * 64;
    int g = wid >> 2;                 // n-group 0..1
    int bx = blockIdx.x, nctas = gridDim.x;

    // tiles for this CTA: t = bx + nctas * i (nctas multiple of 8 -> mg fixed)
    int ntiles_mine = (bx < NTILES % nctas || NTILES % nctas == 0)
                      ? (NTILES + nctas - 1 - bx) / nctas
                      : (NTILES - 1 - bx) / nctas + 1;
    // (generic formula) number of i with bx + nctas*i < NTILES:
    ntiles_mine = (NTILES - 1 - bx) / nctas + 1;
    int nchunks = ntiles_mine * NKIT;

    float* stats = reinterpret_cast<float*>(smraw + NSTAGE * STAGE_BYTES);
    float* rmaxs = stats;              // [128][2]
    float* rsums = stats + 256;        // [128][2]
    float* segm  = stats + 512;        // [128]

    float c[2][8][4];
    #pragma unroll
    for (int i = 0; i < 2; i++)
        #pragma unroll
        for (int j = 0; j < 8; j++)
            #pragma unroll
            for (int q = 0; q < 4; q++) c[i][j][q] = 0.f;

    auto load_chunk = [&](int s, int gcl) {
        int it = gcl / NKIT;
        int kc = gcl - it * NKIT;
        int tt = bx + nctas * it;
        int mg = tt & 7, nt = tt >> 3;
        const __half* Ak = g_Ah + (size_t)(mg * BM) * KPRIME + kc * BKE;
        const __half* Bk = g_Bh + (size_t)(nt * BN) * KPRIME + kc * BKE;
        uint32_t as = sb + s * STAGE_BYTES;
        uint32_t bs = as + 16384;
        #pragma unroll
        for (int i = 0; i < 4; i++) {
            int idx = tid + i * 256;
            int row = idx >> 3, cq = idx & 7;
            cpa16(as + swz((uint32_t)(row * 128 + cq * 16)),
                  Ak + (size_t)row * KPRIME + cq * 8);
        }
        #pragma unroll
        for (int i = 0; i < 4; i++) {
            int idx = tid + i * 256;
            int row = idx >> 3, cq = idx & 7;
            cpa16(bs + swz((uint32_t)(row * 128 + cq * 16)),
                  Bk + (size_t)row * KPRIME + cq * 8);
        }
    };

    load_chunk(0, 0); CP_COMMIT();
    if (nchunks > 1) load_chunk(1, 1);
    CP_COMMIT();

    int sidx = 0;
    for (int gc = 0; gc < nchunks; gc++) {
        CP_WAIT1();
        __syncthreads();
        if (gc + 2 < nchunks) {
            int ns = sidx + 2; if (ns >= NSTAGE) ns -= NSTAGE;
            load_chunk(ns, gc + 2);
        }
        CP_COMMIT();

        uint32_t as = sb + sidx * STAGE_BYTES;
        uint32_t bs = as + 16384;
        #pragma unroll
        for (int kk = 0; kk < 4; kk++) {
            uint32_t afr[2][4], bfr[4][4];
            #pragma unroll
            for (int i = 0; i < 2; i++) {
                int row = wm + i * 16 + (lane & 15);
                int cb = kk * 32 + ((lane >> 4) << 4);
                LDMX4(afr[i], as + swz((uint32_t)(row * 128 + cb)));
            }
            #pragma unroll
            for (int j = 0; j < 4; j++) {
                int row = wn + j * 16 + ((lane >> 4) << 3) + (lane & 7);
                int cb = kk * 32 + (((lane >> 3) & 1) << 4);
                LDMX4(bfr[j], bs + swz((uint32_t)(row * 128 + cb)));
            }
            #pragma unroll
            for (int i = 0; i < 2; i++) {
                #pragma unroll
                for (int j = 0; j < 8; j++) {
                    uint32_t b0 = bfr[j >> 1][(j & 1) * 2];
                    uint32_t b1 = bfr[j >> 1][(j & 1) * 2 + 1];
                    MMA16816(c[i][j], afr[i], b0, b1);
                }
            }
        }
        sidx++; if (sidx >= NSTAGE) sidx = 0;

        // ---- per-tile epilogue (prefetch for next tile already in flight) ----
        int kt = gc;  // position within tile
        {
            int it = gc / NKIT;
            kt = gc - it * NKIT;
            if (kt == NKIT - 1) {
                int tt = bx + nctas * it;
                int mg = tt & 7, nt = tt >> 3;
                int m0 = mg * BM, n0 = nt * BN;

                // store logits
                #pragma unroll
                for (int i = 0; i < 2; i++) {
                    int mrow = m0 + wm + i * 16 + (lane >> 2);
                    #pragma unroll
                    for (int j = 0; j < 8; j++) {
                        int n = n0 + wn + j * 8 + (lane & 3) * 2;
                        if (n < NV) {
                            float2 v0 = make_float2(c[i][j][0], c[i][j][1]);
                            float2 v1 = make_float2(c[i][j][2], c[i][j][3]);
                            *reinterpret_cast<float2*>(out + (size_t)mrow * NV + n) = v0;
                            *reinterpret_cast<float2*>(out + (size_t)(mrow + 8) * NV + n) = v1;
                        }
                    }
                }

                // fused softmax segment stats (mask n >= NV)
                const float NEG = -1e30f;
                float lm[2][2];
                #pragma unroll
                for (int i = 0; i < 2; i++)
                    #pragma unroll
                    for (int h = 0; h < 2; h++) {
                        float v = NEG;
                        #pragma unroll
                        for (int j = 0; j < 8; j++) {
                            int n = n0 + wn + j * 8 + (lane & 3) * 2;
                            float x0 = (n     < NV) ? c[i][j][2 * h]     : NEG;
                            float x1 = (n + 1 < NV) ? c[i][j][2 * h + 1] : NEG;
                            v = fmaxf(v, fmaxf(x0, x1));
                        }
                        v = fmaxf(v, __shfl_xor_sync(0xffffffffu, v, 1));
                        v = fmaxf(v, __shfl_xor_sync(0xffffffffu, v, 2));
                        lm[i][h] = v;
                    }
                if ((lane & 3) == 0) {
                    #pragma unroll
                    for (int i = 0; i < 2; i++)
                        #pragma unroll
                        for (int h = 0; h < 2; h++)
                            rmaxs[(wm + i * 16 + h * 8 + (lane >> 2)) * 2 + g] = lm[i][h];
                }
                __syncthreads();
                if (tid < 128)
                    segm[tid] = fmaxf(rmaxs[tid * 2], rmaxs[tid * 2 + 1]);
                __syncthreads();

                #pragma unroll
                for (int i = 0; i < 2; i++)
                    #pragma unroll
                    for (int h = 0; h < 2; h++) {
                        float M = segm[wm + i * 16 + h * 8 + (lane >> 2)];
                        float s = 0.f;
                        #pragma unroll
                        for (int j = 0; j < 8; j++) {
                            int n = n0 + wn + j * 8 + (lane & 3) * 2;
                            if (n     < NV) s += expf(c[i][j][2 * h]     - M);
                            if (n + 1 < NV) s += expf(c[i][j][2 * h + 1] - M);
                        }
                        s += __shfl_xor_sync(0xffffffffu, s, 1);
                        s += __shfl_xor_sync(0xffffffffu, s, 2);
                        if ((lane & 3) == 0)
                            rsums[(wm + i * 16 + h * 8 + (lane >> 2)) * 2 + g] = s;
                    }
                __syncthreads();
                if (tid < 128) {
                    float s = rsums[tid * 2] + rsums[tid * 2 + 1];
                    g_smax[(size_t)nt * NB + m0 + tid] = segm[tid];
                    g_ssum[(size_t)nt * NB + m0 + tid] = s;
                }

                // reset accumulators for the next tile
                #pragma unroll
                for (int i = 0; i < 2; i++)
                    #pragma unroll
                    for (int j = 0; j < 8; j++)
                        #pragma unroll
                        for (int q = 0; q < 4; q++) c[i][j][q] = 0.f;
            }
        }
    }
}

// ---------------- final: merge stats + normalize + exact top-10 -----------------
__global__ void __launch_bounds__(512) k_final(float* __restrict__ logits,
                                               float* __restrict__ out_idx) {
    int b = blockIdx.x, t = threadIdx.x;
    float* row = logits + (size_t)b * NV;
    float4* row4 = reinterpret_cast<float4*>(row);

    __shared__ float sm[512], ss[512];
    {
        float m = (t < NTN) ? g_smax[(size_t)t * NB + b] : -1e30f;
        float s = (t < NTN) ? g_ssum[(size_t)t * NB + b] : 0.f;
        sm[t] = m; ss[t] = s;
        __syncthreads();
        for (int st = 256; st > 0; st >>= 1) {
            if (t < st) {
                float m1 = sm[t], s1 = ss[t];
                float m2 = sm[t + st], s2 = ss[t + st];
                float mm = fmaxf(m1, m2);
                ss[t] = s1 * expf(m1 - mm) + s2 * expf(m2 - mm);
                sm[t] = mm;
            }
            __syncthreads();
        }
    }
    float M = sm[0], S = ss[0];
    float invS = 1.0f / S;
    __syncthreads();

    float tv[NTOPK];
    int ti[NTOPK];
    #pragma unroll
    for (int q = 0; q < NTOPK; q++) { tv[q] = -INFINITY; ti[q] = 0x7fffffff; }

    for (int v4 = t; v4 < NV / 4; v4 += 512) {
        float4 x4 = row4[v4];
        float xs[4] = {x4.x, x4.y, x4.z, x4.w};
        #pragma unroll
        for (int e = 0; e < 4; e++) {
            float x = xs[e];
            if (x > tv[NTOPK - 1]) {
                float nv = x; int ni = v4 * 4 + e;
                #pragma unroll
                for (int q = 0; q < NTOPK; q++) {
                    if (nv > tv[q]) {
                        float fv = tv[q]; tv[q] = nv; nv = fv;
                        int ii = ti[q]; ti[q] = ni; ni = ii;
                    }
                }
            }
        }
        x4.x = expf(x4.x - M) * invS;
        x4.y = expf(x4.y - M) * invS;
        x4.z = expf(x4.z - M) * invS;
        x4.w = expf(x4.w - M) * invS;
        row4[v4] = x4;
    }

    __shared__ float rv[512];
    __shared__ int ri[512];
    for (int r10 = 0; r10 < NTOPK; r10++) {
        rv[t] = tv[0]; ri[t] = ti[0];
        __syncthreads();
        for (int st = 256; st > 0; st >>= 1) {
            if (t < st) {
                float v2 = rv[t + st]; int i2 = ri[t + st];
                if (v2 > rv[t] || (v2 == rv[t] && i2 < ri[t])) { rv[t] = v2; ri[t] = i2; }
            }
            __syncthreads();
        }
        float bv = rv[0]; int bi = ri[0];
        if (t == 0) out_idx[(size_t)b * NTOPK + r10] = (float)bi;
        if (tv[0] == bv && ti[0] == bi) {
            #pragma unroll
            for (int q = 0; q < NTOPK - 1; q++) { tv[q] = tv[q + 1]; ti[q] = ti[q + 1]; }
            tv[NTOPK - 1] = -INFINITY; ti[NTOPK - 1] = 0x7fffffff;
        }
        __syncthreads();
    }
}

// ---------------- host launcher --------------------------------------------------
extern "C" void kernel_launch(void* const* d_in, const int* in_sizes, int n_in,
                              void* d_out, int out_size) {
    const int*   wl_ids = (const int*)  d_in[0];
    const int*   wr_ids = (const int*)  d_in[1];
    const int*   cl_ids = (const int*)  d_in[2];
    const int*   cr_ids = (const int*)  d_in[3];
    const float* wemb   = (const float*)d_in[4];
    const float* cemb   = (const float*)d_in[5];
    const float* W_a    = (const float*)d_in[6];
    const float* b_a    = (const float*)d_in[7];
    const float* W_c    = (const float*)d_in[8];
    const float* b_c    = (const float*)d_in[9];
    float* out = (float*)d_out;

    cudaFuncSetAttribute(k_gemm_hmma,
                         cudaFuncAttributeMaxDynamicSharedMemorySize, SMEM_DYN);

    int nsm = 148;
    cudaDeviceGetAttribute(&nsm, cudaDevAttrMultiProcessorCount, 0);
    int nctas = 2 * nsm;            // multiple of 8 for both 148 and 152 SMs

    float* g_words_p;  cudaGetSymbolAddress((void**)&g_words_p,  g_words);
    float* g_align_p;  cudaGetSymbolAddress((void**)&g_align_p,  g_align);
    float* g_concat_p; cudaGetSymbolAddress((void**)&g_concat_p, g_concat);

    // 0: fused gather + B' conversion
    k_prep<<<25512, 256>>>(wl_ids, wr_ids, wemb, cemb);
    // 1: align GEMM
    k_gemm_small64<0><<<dim3(4, 32), 128>>>(g_words_p, W_a, b_a, g_align_p,
                                            2048, ND, ND);
    // 2: fused attention (both sides) + concat
    k_attend2<<<NB, 256>>>(cl_ids, cr_ids, cemb);
    // 3: phrase GEMM with fused A' split epilogue
    k_gemm_small64<1><<<dim3(4, 16), 128>>>(g_concat_p, W_c, b_c, nullptr,
                                            NB, ND, 2 * ND);
    // 4: persistent tensor-core GEMM with fused stats
    k_gemm_hmma<<<nctas, 256, SMEM_DYN>>>(out);
    // 5: merge + normalize + top-10
    k_final<<<NB, 512>>>(out, out + (size_t)NB * NV);
}

// round 10
// speedup vs baseline: 1.0093x; 1.0093x over previous
#include <cuda_runtime.h>
#include <cuda_fp16.h>
#include <cstdint>
#include <math.h>

#define NB    1024
#define ND    256
#define NV    50000
#define NC    64
#define NTOPK 10

#define KPRIME 768            // 3 * ND virtual K (fp16 2-split, 3 products)
#define BM 128
#define BN 128
#define BKE 64                // fp16 elements per k-chunk (128 B rows)
#define NKIT (KPRIME / BKE)   // 12
#define NTN 392               // n-tiles (50176 / 128)
#define NPADN (NTN * BN)      // 50176

// ---------------- scratch (device globals) ----------------------------------
__device__ __align__(16) float g_words [2048 * ND];
__device__ __align__(16) float g_align [2048 * ND];
__device__ __align__(16) float g_concat[NB * 2 * ND];
__device__ __align__(16) __half g_Ah[(size_t)NB * KPRIME];      // 1.5 MB
__device__ __align__(16) __half g_Bh[(size_t)NPADN * KPRIME];   // 77 MB
__device__ float g_smax[(size_t)NTN * NB];
__device__ float g_ssum[(size_t)NTN * NB];

// ---------------- helpers -----------------------------------------------------
__device__ __forceinline__ uint32_t swz(uint32_t b) { return b ^ ((b >> 3) & 0x70); }

__device__ __forceinline__ void fma_f32x2(unsigned long long &d,
                                          unsigned long long a,
                                          unsigned long long b) {
    asm("fma.rn.f32x2 %0, %1, %2, %0;" : "+l"(d) : "l"(a), "l"(b));
}
__device__ __forceinline__ unsigned long long dup_f32(float a) {
    unsigned int u = __float_as_uint(a);
    unsigned long long r;
    asm("mov.b64 %0, {%1, %1};" : "=l"(r) : "r"(u));
    return r;
}
__device__ __forceinline__ float2 unpack_f32x2(unsigned long long v) {
    float2 f;
    f.x = __uint_as_float((unsigned int)(v & 0xffffffffull));
    f.y = __uint_as_float((unsigned int)(v >> 32));
    return f;
}
__device__ __forceinline__ uint32_t cvta_smem(const void* p) {
    uint32_t a;
    asm("{ .reg .u64 t; cvta.to.shared.u64 t, %1; cvt.u32.u64 %0, t; }"
        : "=r"(a) : "l"(p));
    return a;
}
__device__ __forceinline__ void cpa16(uint32_t d, const void* s) {
    asm volatile("cp.async.cg.shared.global [%0], [%1], 16;" :: "r"(d), "l"(s));
}
#define CP_COMMIT() asm volatile("cp.async.commit_group;" ::: "memory")
#define CP_WAIT1()  asm volatile("cp.async.wait_group 1;" ::: "memory")

#define LDMX4(r, a) \
    asm volatile("ldmatrix.sync.aligned.m8n8.x4.shared.b16 {%0,%1,%2,%3}, [%4];" \
        : "=r"((r)[0]), "=r"((r)[1]), "=r"((r)[2]), "=r"((r)[3]) : "r"(a))

#define MMA16816(c, a, b0, b1) \
    asm volatile("mma.sync.aligned.m16n8k16.row.col.f32.f16.f16.f32 " \
        "{%0,%1,%2,%3}, {%4,%5,%6,%7}, {%8,%9}, {%0,%1,%2,%3};" \
        : "+f"((c)[0]), "+f"((c)[1]), "+f"((c)[2]), "+f"((c)[3]) \
        : "r"((a)[0]), "r"((a)[1]), "r"((a)[2]), "r"((a)[3]), "r"(b0), "r"(b1))

// ---------------- fp16 2-split helpers ------------------------------------------
__device__ __forceinline__ void split2(float x, float& h, float& l) {
    __half hh = __float2half_rn(x);
    h = __half2float(hh);
    l = x - h;
}
__device__ __forceinline__ __half2 mkh2(float a, float b) {
    return __halves2half2(__float2half_rn(a), __float2half_rn(b));
}

// ---------------- prep: fused gather_words + convB ------------------------------
__global__ void k_prep(const int* __restrict__ wl,
                       const int* __restrict__ wr,
                       const float* __restrict__ wemb,
                       const float* __restrict__ cemb) {
    if (blockIdx.x < 512) {
        int idx = blockIdx.x * 256 + threadIdx.x;
        int r = idx >> 6, q = idx & 63;
        int id = (r < NB) ? wl[r] : wr[r - NB];
        const float4* src = reinterpret_cast<const float4*>(wemb);
        float4* dst = reinterpret_cast<float4*>(g_words);
        dst[(size_t)r * 64 + q] = src[(size_t)id * 64 + q];
        return;
    }
    size_t tid = (size_t)(blockIdx.x - 512) * 256 + threadIdx.x;  // 50000*128 total
    int n = (int)(tid >> 7);
    int k = (int)(tid & 127) * 2;
    float2 v = *reinterpret_cast<const float2*>(cemb + (size_t)n * ND + k);
    float h0, l0, h1, l1;
    split2(v.x, h0, l0);
    split2(v.y, h1, l1);
    __half2* row = reinterpret_cast<__half2*>(g_Bh + (size_t)n * KPRIME);
    row[k / 2]         = mkh2(h0, h1);                       // b0
    row[(256 + k) / 2] = mkh2(l0 * 32.f, l1 * 32.f);         // b1*32
    row[(512 + k) / 2] = mkh2(h0 * 0.03125f, h1 * 0.03125f); // b0/32
}

// ---------------- fp32 32x64-tile GEMM; SPLIT_OUT=1 writes fp16 split A' --------
// 128 threads (tx 8 x ty 16), per thread 2 rows x 8 cols. N must be 256.
template<int SPLIT_OUT>
__global__ void __launch_bounds__(128) k_gemm_small(
        const float* __restrict__ A, const float* __restrict__ Bm,
        const float* __restrict__ bias, float* __restrict__ Cc,
        int M, int N, int K) {
    const int TBK = 16;
    __shared__ __align__(16) float As[TBK][32];
    __shared__ __align__(16) float Bs[TBK][64];
    int tid = threadIdx.x;
    int tx = tid & 7, ty = tid >> 3;
    int m0 = blockIdx.y * 32;
    int n0 = blockIdx.x * 64;

    unsigned long long acc[2][4];
    #pragma unroll
    for (int i = 0; i < 2; i++)
        #pragma unroll
        for (int j = 0; j < 4; j++) acc[i][j] = 0ull;

    for (int k0 = 0; k0 < K; k0 += TBK) {
        // A tile: 32 rows x 16 k = 128 float4, transpose-stored
        {
            int row = tid >> 2, kv = tid & 3;
            float4 v = *reinterpret_cast<const float4*>(
                A + (size_t)(m0 + row) * K + k0 + kv * 4);
            As[kv * 4 + 0][row] = v.x;
            As[kv * 4 + 1][row] = v.y;
            As[kv * 4 + 2][row] = v.z;
            As[kv * 4 + 3][row] = v.w;
        }
        // B tile: 16 k x 64 n = 256 float4
        #pragma unroll
        for (int p = 0; p < 2; p++) {
            int f = tid + p * 128;
            int kk = f >> 4, nv = f & 15;
            float4 v = *reinterpret_cast<const float4*>(
                Bm + (size_t)(k0 + kk) * N + n0 + nv * 4);
            *reinterpret_cast<float4*>(&Bs[kk][nv * 4]) = v;
        }
        __syncthreads();

        #pragma unroll
        for (int k = 0; k < TBK; k++) {
            float a0 = As[k][ty * 2], a1 = As[k][ty * 2 + 1];
            const ulonglong2* bp = reinterpret_cast<const ulonglong2*>(&Bs[k][tx * 8]);
            ulonglong2 b01 = bp[0], b23 = bp[1];
            unsigned long long bf[4] = {b01.x, b01.y, b23.x, b23.y};
            unsigned long long ad0 = dup_f32(a0), ad1 = dup_f32(a1);
            #pragma unroll
            for (int j = 0; j < 4; j++) {
                fma_f32x2(acc[0][j], ad0, bf[j]);
                fma_f32x2(acc[1][j], ad1, bf[j]);
            }
        }
        __syncthreads();
    }

    #pragma unroll
    for (int i = 0; i < 2; i++) {
        int m = m0 + ty * 2 + i;
        #pragma unroll
        for (int j = 0; j < 4; j++) {
            int n = n0 + tx * 8 + j * 2;
            float2 r = unpack_f32x2(acc[i][j]);
            r.x = tanhf(r.x + bias[n]);
            r.y = tanhf(r.y + bias[n + 1]);
            if (SPLIT_OUT) {
                float h0, l0, h1, l1;
                split2(r.x, h0, l0);
                split2(r.y, h1, l1);
                __half2* row = reinterpret_cast<__half2*>(g_Ah + (size_t)m * KPRIME);
                row[n / 2]         = mkh2(h0, h1);
                row[(256 + n) / 2] = mkh2(h0 * 0.03125f, h1 * 0.03125f);
                row[(512 + n) / 2] = mkh2(l0 * 32.f, l1 * 32.f);
            } else {
                *reinterpret_cast<float2*>(Cc + (size_t)m * N + n) = r;
            }
        }
    }
}

// ---------------- fused attention (both sides) + concat -------------------------
__global__ void k_attend2(const int* __restrict__ cand_l,
                          const int* __restrict__ cand_r,
                          const float* __restrict__ cemb) {
    int b = blockIdx.x;
    int t = threadIdx.x, w = t >> 5, l = t & 31;

    __shared__ float al[2][ND];
    __shared__ int ids_sm[2][NC];
    __shared__ float sc[2][NC];
    __shared__ float att[2][NC];

    al[0][t] = g_align[(size_t)b * ND + t];
    al[1][t] = g_align[(size_t)(NB + b) * ND + t];
    if (t < NC)            ids_sm[0][t]      = cand_r[b * NC + t];        // side 0
    else if (t < 2 * NC)   ids_sm[1][t - NC] = cand_l[b * NC + (t - NC)]; // side 1
    __syncthreads();

    #pragma unroll
    for (int side = 0; side < 2; side++) {
        #pragma unroll
        for (int ci = 0; ci < 8; ci++) {
            int c = w * 8 + ci;
            const float* e = cemb + (size_t)ids_sm[side][c] * ND;
            float p = 0.f;
            #pragma unroll
            for (int j = 0; j < 8; j++) {
                int d = l + 32 * j;
                p += e[d] * al[side][d];
            }
            #pragma unroll
            for (int o = 16; o > 0; o >>= 1) p += __shfl_down_sync(0xffffffffu, p, o);
            if (l == 0) sc[side][c] = p;
        }
    }
    __syncthreads();

    if (t < 64) {
        int side = w;
        float s0 = sc[side][l], s1 = sc[side][l + 32];
        float mx = fmaxf(s0, s1);
        #pragma unroll
        for (int o = 16; o > 0; o >>= 1) mx = fmaxf(mx, __shfl_xor_sync(0xffffffffu, mx, o));
        float e0 = expf(s0 - mx), e1 = expf(s1 - mx);
        float sum = e0 + e1;
        #pragma unroll
        for (int o = 16; o > 0; o >>= 1) sum += __shfl_xor_sync(0xffffffffu, sum, o);
        att[side][l] = e0 / sum;
        att[side][l + 32] = e1 / sum;
    }
    __syncthreads();

    float a0 = 0.f, a1 = 0.f;
    #pragma unroll 8
    for (int c = 0; c < NC; c++) {
        a0 += att[0][c] * __ldg(cemb + (size_t)ids_sm[0][c] * ND + t);
        a1 += att[1][c] * __ldg(cemb + (size_t)ids_sm[1][c] * ND + t);
    }
    float wsum = g_words[(size_t)b * ND + t] + g_words[(size_t)(NB + b) * ND + t];
    g_concat[(size_t)b * 2 * ND + t]      = wsum;
    g_concat[(size_t)b * 2 * ND + ND + t] = a0 + a1;
}

// ---------------- HMMA fp16 split GEMM with fused softmax stats (R8 version) ----
#define STAGE_BYTES 32768     // A 16KB + B 16KB
#define NSTAGE 3
#define SMEM_DYN (NSTAGE * STAGE_BYTES)
__global__ void __launch_bounds__(256, 2) k_gemm_hmma(float* __restrict__ out) {
    extern __shared__ __align__(128) char smraw[];
    uint32_t sb = cvta_smem(smraw);
    int tid = threadIdx.x, wid = tid >> 5, lane = tid & 31;
    int m0 = blockIdx.x * BM;
    int n0 = blockIdx.y * BN;
    int nt = blockIdx.y;
    int wm = (wid & 3) * 32;
    int wn = (wid >> 2) * 64;
    int g = wid >> 2;                 // n-group 0..1

    const __half* Ag = g_Ah + (size_t)m0 * KPRIME;
    const __half* Bg = g_Bh + (size_t)n0 * KPRIME;

    float c[2][8][4];
    #pragma unroll
    for (int i = 0; i < 2; i++)
        #pragma unroll
        for (int j = 0; j < 8; j++)
            #pragma unroll
            for (int q = 0; q < 4; q++) c[i][j][q] = 0.f;

    auto load_stage = [&](int s, int kc) {
        uint32_t as = sb + s * STAGE_BYTES;
        uint32_t bs = as + 16384;
        const __half* Ak = Ag + kc * BKE;
        const __half* Bk = Bg + kc * BKE;
        #pragma unroll
        for (int i = 0; i < 4; i++) {
            int idx = tid + i * 256;
            int row = idx >> 3, cq = idx & 7;
            cpa16(as + swz((uint32_t)(row * 128 + cq * 16)),
                  Ak + (size_t)row * KPRIME + cq * 8);
        }
        #pragma unroll
        for (int i = 0; i < 4; i++) {
            int idx = tid + i * 256;
            int row = idx >> 3, cq = idx & 7;
            cpa16(bs + swz((uint32_t)(row * 128 + cq * 16)),
                  Bk + (size_t)row * KPRIME + cq * 8);
        }
    };

    load_stage(0, 0); CP_COMMIT();
    load_stage(1, 1); CP_COMMIT();

    int sidx = 0;
    for (int kt = 0; kt < NKIT; kt++) {
        CP_WAIT1();
        __syncthreads();
        if (kt + 2 < NKIT) {
            int ns = sidx + 2; if (ns >= NSTAGE) ns -= NSTAGE;
            load_stage(ns, kt + 2);
        }
        CP_COMMIT();

        uint32_t as = sb + sidx * STAGE_BYTES;
        uint32_t bs = as + 16384;
        #pragma unroll
        for (int kk = 0; kk < 4; kk++) {
            uint32_t afr[2][4], bfr[4][4];
            #pragma unroll
            for (int i = 0; i < 2; i++) {
                int row = wm + i * 16 + (lane & 15);
                int cb = kk * 32 + ((lane >> 4) << 4);
                LDMX4(afr[i], as + swz((uint32_t)(row * 128 + cb)));
            }
            #pragma unroll
            for (int j = 0; j < 4; j++) {
                int row = wn + j * 16 + ((lane >> 4) << 3) + (lane & 7);
                int cb = kk * 32 + (((lane >> 3) & 1) << 4);
                LDMX4(bfr[j], bs + swz((uint32_t)(row * 128 + cb)));
            }
            #pragma unroll
            for (int i = 0; i < 2; i++) {
                #pragma unroll
                for (int j = 0; j < 8; j++) {
                    uint32_t b0 = bfr[j >> 1][(j & 1) * 2];
                    uint32_t b1 = bfr[j >> 1][(j & 1) * 2 + 1];
                    MMA16816(c[i][j], afr[i], b0, b1);
                }
            }
        }
        sidx++; if (sidx >= NSTAGE) sidx = 0;
    }

    // ---- store logits ----
    #pragma unroll
    for (int i = 0; i < 2; i++) {
        int mrow = m0 + wm + i * 16 + (lane >> 2);
        #pragma unroll
        for (int j = 0; j < 8; j++) {
            int n = n0 + wn + j * 8 + (lane & 3) * 2;
            if (n < NV) {
                float2 v0 = make_float2(c[i][j][0], c[i][j][1]);
                float2 v1 = make_float2(c[i][j][2], c[i][j][3]);
                *reinterpret_cast<float2*>(out + (size_t)mrow * NV + n) = v0;
                *reinterpret_cast<float2*>(out + (size_t)(mrow + 8) * NV + n) = v1;
            }
        }
    }

    // ---- fused softmax segment stats (mask n >= NV) ----
    float* rmaxs = reinterpret_cast<float*>(smraw);        // [128][2]
    float* rsums = rmaxs + 256;                            // [128][2]
    float* segm  = rsums + 256;                            // [128]

    const float NEG = -1e30f;
    float lm[2][2];
    #pragma unroll
    for (int i = 0; i < 2; i++)
        #pragma unroll
        for (int h = 0; h < 2; h++) {
            float v = NEG;
            #pragma unroll
            for (int j = 0; j < 8; j++) {
                int n = n0 + wn + j * 8 + (lane & 3) * 2;
                float x0 = (n     < NV) ? c[i][j][2 * h]     : NEG;
                float x1 = (n + 1 < NV) ? c[i][j][2 * h + 1] : NEG;
                v = fmaxf(v, fmaxf(x0, x1));
            }
            v = fmaxf(v, __shfl_xor_sync(0xffffffffu, v, 1));
            v = fmaxf(v, __shfl_xor_sync(0xffffffffu, v, 2));
            lm[i][h] = v;
        }
    if ((lane & 3) == 0) {
        #pragma unroll
        for (int i = 0; i < 2; i++)
            #pragma unroll
            for (int h = 0; h < 2; h++)
                rmaxs[(wm + i * 16 + h * 8 + (lane >> 2)) * 2 + g] = lm[i][h];
    }
    __syncthreads();
    if (tid < 128) {
        segm[tid] = fmaxf(rmaxs[tid * 2], rmaxs[tid * 2 + 1]);
    }
    __syncthreads();

    #pragma unroll
    for (int i = 0; i < 2; i++)
        #pragma unroll
        for (int h = 0; h < 2; h++) {
            float M = segm[wm + i * 16 + h * 8 + (lane >> 2)];
            float s = 0.f;
            #pragma unroll
            for (int j = 0; j < 8; j++) {
                int n = n0 + wn + j * 8 + (lane & 3) * 2;
                if (n     < NV) s += expf(c[i][j][2 * h]     - M);
                if (n + 1 < NV) s += expf(c[i][j][2 * h + 1] - M);
            }
            s += __shfl_xor_sync(0xffffffffu, s, 1);
            s += __shfl_xor_sync(0xffffffffu, s, 2);
            if ((lane & 3) == 0)
                rsums[(wm + i * 16 + h * 8 + (lane >> 2)) * 2 + g] = s;
        }
    __syncthreads();
    if (tid < 128) {
        float s = rsums[tid * 2] + rsums[tid * 2 + 1];
        g_smax[(size_t)nt * NB + m0 + tid] = segm[tid];
        g_ssum[(size_t)nt * NB + m0 + tid] = s;
    }
}

// ---------------- final: merge stats + normalize + exact top-10 -----------------
__global__ void __launch_bounds__(512) k_final(float* __restrict__ logits,
                                               float* __restrict__ out_idx) {
    int b = blockIdx.x, t = threadIdx.x;
    float* row = logits + (size_t)b * NV;
    float4* row4 = reinterpret_cast<float4*>(row);

    __shared__ float sm[512], ss[512];
    {
        float m = (t < NTN) ? g_smax[(size_t)t * NB + b] : -1e30f;
        float s = (t < NTN) ? g_ssum[(size_t)t * NB + b] : 0.f;
        sm[t] = m; ss[t] = s;
        __syncthreads();
        for (int st = 256; st > 0; st >>= 1) {
            if (t < st) {
                float m1 = sm[t], s1 = ss[t];
                float m2 = sm[t + st], s2 = ss[t + st];
                float mm = fmaxf(m1, m2);
                ss[t] = s1 * expf(m1 - mm) + s2 * expf(m2 - mm);
                sm[t] = mm;
            }
            __syncthreads();
        }
    }
    float M = sm[0], S = ss[0];
    float invS = 1.0f / S;
    __syncthreads();

    float tv[NTOPK];
    int ti[NTOPK];
    #pragma unroll
    for (int q = 0; q < NTOPK; q++) { tv[q] = -INFINITY; ti[q] = 0x7fffffff; }

    for (int v4 = t; v4 < NV / 4; v4 += 512) {
        float4 x4 = row4[v4];
        float xs[4] = {x4.x, x4.y, x4.z, x4.w};
        #pragma unroll
        for (int e = 0; e < 4; e++) {
            float x = xs[e];
            if (x > tv[NTOPK - 1]) {
                float nv = x; int ni = v4 * 4 + e;
                #pragma unroll
                for (int q = 0; q < NTOPK; q++) {
                    if (nv > tv[q]) {
                        float fv = tv[q]; tv[q] = nv; nv = fv;
                        int ii = ti[q]; ti[q] = ni; ni = ii;
                    }
                }
            }
        }
        x4.x = expf(x4.x - M) * invS;
        x4.y = expf(x4.y - M) * invS;
        x4.z = expf(x4.z - M) * invS;
        x4.w = expf(x4.w - M) * invS;
        row4[v4] = x4;
    }

    __shared__ float rv[512];
    __shared__ int ri[512];
    for (int r10 = 0; r10 < NTOPK; r10++) {
        rv[t] = tv[0]; ri[t] = ti[0];
        __syncthreads();
        for (int st = 256; st > 0; st >>= 1) {
            if (t < st) {
                float v2 = rv[t + st]; int i2 = ri[t + st];
                if (v2 > rv[t] || (v2 == rv[t] && i2 < ri[t])) { rv[t] = v2; ri[t] = i2; }
            }
            __syncthreads();
        }
        float bv = rv[0]; int bi = ri[0];
        if (t == 0) out_idx[(size_t)b * NTOPK + r10] = (float)bi;
        if (tv[0] == bv && ti[0] == bi) {
            #pragma unroll
            for (int q = 0; q < NTOPK - 1; q++) { tv[q] = tv[q + 1]; ti[q] = ti[q + 1]; }
            tv[NTOPK - 1] = -INFINITY; ti[NTOPK - 1] = 0x7fffffff;
        }
        __syncthreads();
    }
}

// ---------------- host launcher --------------------------------------------------
extern "C" void kernel_launch(void* const* d_in, const int* in_sizes, int n_in,
                              void* d_out, int out_size) {
    const int*   wl_ids = (const int*)  d_in[0];
    const int*   wr_ids = (const int*)  d_in[1];
    const int*   cl_ids = (const int*)  d_in[2];
    const int*   cr_ids = (const int*)  d_in[3];
    const float* wemb   = (const float*)d_in[4];
    const float* cemb   = (const float*)d_in[5];
    const float* W_a    = (const float*)d_in[6];
    const float* b_a    = (const float*)d_in[7];
    const float* W_c    = (const float*)d_in[8];
    const float* b_c    = (const float*)d_in[9];
    float* out = (float*)d_out;

    cudaFuncSetAttribute(k_gemm_hmma,
                         cudaFuncAttributeMaxDynamicSharedMemorySize, SMEM_DYN);

    float* g_words_p;  cudaGetSymbolAddress((void**)&g_words_p,  g_words);
    float* g_align_p;  cudaGetSymbolAddress((void**)&g_align_p,  g_align);
    float* g_concat_p; cudaGetSymbolAddress((void**)&g_concat_p, g_concat);

    // 0: fused gather + B' conversion
    k_prep<<<25512, 256>>>(wl_ids, wr_ids, wemb, cemb);
    // 1: align GEMM (2048x256, K=256) — 256 CTAs
    k_gemm_small<0><<<dim3(4, 64), 128>>>(g_words_p, W_a, b_a, g_align_p,
                                          2048, ND, ND);
    // 2: fused attention (both sides) + concat
    k_attend2<<<NB, 256>>>(cl_ids, cr_ids, cemb);
    // 3: phrase GEMM with fused A' split epilogue (1024x256, K=512) — 128 CTAs
    k_gemm_small<1><<<dim3(4, 32), 128>>>(g_concat_p, W_c, b_c, nullptr,
                                          NB, ND, 2 * ND);
    // 4: tensor-core GEMM with fused stats
    k_gemm_hmma<<<dim3(8, NTN), 256, SMEM_DYN>>>(out);
    // 5: merge + normalize + top-10
    k_final<<<NB, 512>>>(out, out + (size_t)NB * NV);
}

// round 11
// speedup vs baseline: 1.0751x; 1.0651x over previous
#include <cuda_runtime.h>
#include <cuda_fp16.h>
#include <cstdint>
#include <math.h>

#define NB    1024
#define ND    256
#define NV    50000
#define NC    64
#define NTOPK 10

#define KPRIME 768            // 3 * ND virtual K (fp16 2-split, 3 products)
#define BM 128
#define BN 128
#define BKE 64                // fp16 elements per k-chunk (128 B rows)
#define NKIT (KPRIME / BKE)   // 12
#define NTN 392               // n-tiles (50176 / 128)
#define NPADN (NTN * BN)      // 50176

// ---------------- scratch (device globals) ----------------------------------
__device__ __align__(16) float g_words [2048 * ND];
__device__ __align__(16) float g_align [2048 * ND];
__device__ __align__(16) float g_aggre [2048 * ND];
__device__ __align__(16) float g_concat[NB * 2 * ND];
__device__ __align__(16) __half g_Ah[(size_t)NB * KPRIME];      // 1.5 MB
__device__ __align__(16) __half g_Bh[(size_t)NPADN * KPRIME];   // 77 MB
__device__ float g_smax[(size_t)NTN * NB];
__device__ float g_ssum[(size_t)NTN * NB];

// ---------------- helpers -----------------------------------------------------
__device__ __forceinline__ uint32_t swz(uint32_t b) { return b ^ ((b >> 3) & 0x70); }

__device__ __forceinline__ void fma_f32x2(unsigned long long &d,
                                          unsigned long long a,
                                          unsigned long long b) {
    asm("fma.rn.f32x2 %0, %1, %2, %0;" : "+l"(d) : "l"(a), "l"(b));
}
__device__ __forceinline__ unsigned long long dup_f32(float a) {
    unsigned int u = __float_as_uint(a);
    unsigned long long r;
    asm("mov.b64 %0, {%1, %1};" : "=l"(r) : "r"(u));
    return r;
}
__device__ __forceinline__ float2 unpack_f32x2(unsigned long long v) {
    float2 f;
    f.x = __uint_as_float((unsigned int)(v & 0xffffffffull));
    f.y = __uint_as_float((unsigned int)(v >> 32));
    return f;
}
__device__ __forceinline__ uint32_t cvta_smem(const void* p) {
    uint32_t a;
    asm("{ .reg .u64 t; cvta.to.shared.u64 t, %1; cvt.u32.u64 %0, t; }"
        : "=r"(a) : "l"(p));
    return a;
}
__device__ __forceinline__ void cpa16(uint32_t d, const void* s) {
    asm volatile("cp.async.cg.shared.global [%0], [%1], 16;" :: "r"(d), "l"(s));
}
#define CP_COMMIT() asm volatile("cp.async.commit_group;" ::: "memory")
#define CP_WAIT1()  asm volatile("cp.async.wait_group 1;" ::: "memory")

#define LDMX4(r, a) \
    asm volatile("ldmatrix.sync.aligned.m8n8.x4.shared.b16 {%0,%1,%2,%3}, [%4];" \
        : "=r"((r)[0]), "=r"((r)[1]), "=r"((r)[2]), "=r"((r)[3]) : "r"(a))

#define MMA16816(c, a, b0, b1) \
    asm volatile("mma.sync.aligned.m16n8k16.row.col.f32.f16.f16.f32 " \
        "{%0,%1,%2,%3}, {%4,%5,%6,%7}, {%8,%9}, {%0,%1,%2,%3};" \
        : "+f"((c)[0]), "+f"((c)[1]), "+f"((c)[2]), "+f"((c)[3]) \
        : "r"((a)[0]), "r"((a)[1]), "r"((a)[2]), "r"((a)[3]), "r"(b0), "r"(b1))

// ---------------- fp16 2-split helpers ------------------------------------------
__device__ __forceinline__ void split2(float x, float& h, float& l) {
    __half hh = __float2half_rn(x);
    h = __half2float(hh);
    l = x - h;
}
__device__ __forceinline__ __half2 mkh2(float a, float b) {
    return __halves2half2(__float2half_rn(a), __float2half_rn(b));
}

// ---------------- prep: fused gather_words + convB ------------------------------
__global__ void k_prep(const int* __restrict__ wl,
                       const int* __restrict__ wr,
                       const float* __restrict__ wemb,
                       const float* __restrict__ cemb) {
    if (blockIdx.x < 512) {
        int idx = blockIdx.x * 256 + threadIdx.x;
        int r = idx >> 6, q = idx & 63;
        int id = (r < NB) ? wl[r] : wr[r - NB];
        const float4* src = reinterpret_cast<const float4*>(wemb);
        float4* dst = reinterpret_cast<float4*>(g_words);
        dst[(size_t)r * 64 + q] = src[(size_t)id * 64 + q];
        return;
    }
    size_t tid = (size_t)(blockIdx.x - 512) * 256 + threadIdx.x;  // 50000*128 total
    int n = (int)(tid >> 7);
    int k = (int)(tid & 127) * 2;
    float2 v = *reinterpret_cast<const float2*>(cemb + (size_t)n * ND + k);
    float h0, l0, h1, l1;
    split2(v.x, h0, l0);
    split2(v.y, h1, l1);
    __half2* row = reinterpret_cast<__half2*>(g_Bh + (size_t)n * KPRIME);
    row[k / 2]         = mkh2(h0, h1);                       // b0
    row[(256 + k) / 2] = mkh2(l0 * 32.f, l1 * 32.f);         // b1*32
    row[(512 + k) / 2] = mkh2(h0 * 0.03125f, h1 * 0.03125f); // b0/32
}

// ---------------- pipelined fp32 32x64-tile GEMM (cp.async, 3 stages) -----------
// 128 threads (tx 8 x ty 16), per thread 2 rows x 8 cols, BK=32, N must be 256.
// SPLIT_OUT=1 writes fp16 split A' instead of fp32 C.
#define SGS_A_FLOATS (32 * 36)               // padded A stage (36 floats/row)
#define SGS_B_FLOATS (32 * 64)
#define SGS_FLOATS   (SGS_A_FLOATS + SGS_B_FLOATS)
template<int SPLIT_OUT>
__global__ void __launch_bounds__(128) k_gemm_small(
        const float* __restrict__ A, const float* __restrict__ Bm,
        const float* __restrict__ bias, float* __restrict__ Cc,
        int M, int N, int K) {
    __shared__ __align__(16) float sm[3 * SGS_FLOATS];
    uint32_t sb = cvta_smem(sm);
    int tid = threadIdx.x;
    int tx = tid & 7, ty = tid >> 3;
    int m0 = blockIdx.y * 32;
    int n0 = blockIdx.x * 64;
    int nk = K >> 5;                          // BK = 32

    unsigned long long acc[2][4];
    #pragma unroll
    for (int i = 0; i < 2; i++)
        #pragma unroll
        for (int j = 0; j < 4; j++) acc[i][j] = 0ull;

    auto load_stage = [&](int s, int kc) {
        uint32_t as = sb + s * (SGS_FLOATS * 4);
        uint32_t bs = as + SGS_A_FLOATS * 4;
        int k0 = kc * 32;
        // A: 32 rows x 32 floats = 256 x 16B, 2 per thread
        #pragma unroll
        for (int p = 0; p < 2; p++) {
            int f = tid + p * 128;
            int row = f >> 3, cq = f & 7;     // 8 chunks of 16B per row
            cpa16(as + (uint32_t)(row * 144 + cq * 16),
                  A + (size_t)(m0 + row) * K + k0 + cq * 4);
        }
        // B: 32 k x 64 floats = 512 x 16B, 4 per thread
        #pragma unroll
        for (int p = 0; p < 4; p++) {
            int f = tid + p * 128;
            int kk = f >> 4, nv = f & 15;
            cpa16(bs + (uint32_t)(kk * 256 + nv * 16),
                  Bm + (size_t)(k0 + kk) * N + n0 + nv * 4);
        }
    };

    load_stage(0, 0); CP_COMMIT();
    if (nk > 1) load_stage(1, 1);
    CP_COMMIT();

    int sidx = 0;
    for (int kc = 0; kc < nk; kc++) {
        CP_WAIT1();
        __syncthreads();
        if (kc + 2 < nk) {
            int ns = sidx + 2; if (ns >= 3) ns -= 3;
            load_stage(ns, kc + 2);
        }
        CP_COMMIT();

        const float* As = sm + sidx * SGS_FLOATS;
        const float* Bs = As + SGS_A_FLOATS;
        #pragma unroll
        for (int k = 0; k < 32; k++) {
            float a0 = As[(ty * 2) * 36 + k];
            float a1 = As[(ty * 2 + 1) * 36 + k];
            const ulonglong2* bp =
                reinterpret_cast<const ulonglong2*>(Bs + k * 64 + tx * 8);
            ulonglong2 b01 = bp[0], b23 = bp[1];
            unsigned long long bf[4] = {b01.x, b01.y, b23.x, b23.y};
            unsigned long long ad0 = dup_f32(a0), ad1 = dup_f32(a1);
            #pragma unroll
            for (int j = 0; j < 4; j++) {
                fma_f32x2(acc[0][j], ad0, bf[j]);
                fma_f32x2(acc[1][j], ad1, bf[j]);
            }
        }
        __syncthreads();
        sidx++; if (sidx >= 3) sidx = 0;
    }

    #pragma unroll
    for (int i = 0; i < 2; i++) {
        int m = m0 + ty * 2 + i;
        #pragma unroll
        for (int j = 0; j < 4; j++) {
            int n = n0 + tx * 8 + j * 2;
            float2 r = unpack_f32x2(acc[i][j]);
            r.x = tanhf(r.x + bias[n]);
            r.y = tanhf(r.y + bias[n + 1]);
            if (SPLIT_OUT) {
                float h0, l0, h1, l1;
                split2(r.x, h0, l0);
                split2(r.y, h1, l1);
                __half2* row = reinterpret_cast<__half2*>(g_Ah + (size_t)m * KPRIME);
                row[n / 2]         = mkh2(h0, h1);
                row[(256 + n) / 2] = mkh2(h0 * 0.03125f, h1 * 0.03125f);
                row[(512 + n) / 2] = mkh2(l0 * 32.f, l1 * 32.f);
            } else {
                *reinterpret_cast<float2*>(Cc + (size_t)m * N + n) = r;
            }
        }
    }
}

// ---------------- attention (R8 version) -----------------------------------------
__global__ void k_attend(const int* __restrict__ cand_l,
                         const int* __restrict__ cand_r,
                         const float* __restrict__ cemb) {
    int b = blockIdx.x, side = blockIdx.y;
    int t = threadIdx.x, w = t >> 5, l = t & 31;
    const int* ids = (side == 0) ? (cand_r + b * NC) : (cand_l + b * NC);
    int arow = side * NB + b;

    __shared__ float al[ND];
    __shared__ int ids_sm[NC];
    __shared__ float sc[NC];
    __shared__ float att[NC];

    al[t] = g_align[(size_t)arow * ND + t];
    if (t < NC) ids_sm[t] = ids[t];
    __syncthreads();

    #pragma unroll
    for (int ci = 0; ci < 8; ci++) {
        int c = w * 8 + ci;
        const float* e = cemb + (size_t)ids_sm[c] * ND;
        float p = 0.f;
        #pragma unroll
        for (int j = 0; j < 8; j++) {
            int d = l + 32 * j;
            p += e[d] * al[d];
        }
        #pragma unroll
        for (int o = 16; o > 0; o >>= 1) p += __shfl_down_sync(0xffffffffu, p, o);
        if (l == 0) sc[c] = p;
    }
    __syncthreads();

    if (t < 32) {
        float s0 = sc[t], s1 = sc[t + 32];
        float mx = fmaxf(s0, s1);
        #pragma unroll
        for (int o = 16; o > 0; o >>= 1) mx = fmaxf(mx, __shfl_xor_sync(0xffffffffu, mx, o));
        float e0 = expf(s0 - mx), e1 = expf(s1 - mx);
        float sum = e0 + e1;
        #pragma unroll
        for (int o = 16; o > 0; o >>= 1) sum += __shfl_xor_sync(0xffffffffu, sum, o);
        att[t] = e0 / sum;
        att[t + 32] = e1 / sum;
    }
    __syncthreads();

    float accd = 0.f;
    #pragma unroll 8
    for (int c = 0; c < NC; c++)
        accd += att[c] * __ldg(cemb + (size_t)ids_sm[c] * ND + t);
    g_aggre[(size_t)arow * ND + t] = accd;
}

// ---------------- concat (R8 version) ---------------------------------------------
__global__ void k_concat() {
    int f = blockIdx.x * 256 + threadIdx.x;
    int b = f >> 7, q = f & 127;
    const float4* W4 = reinterpret_cast<const float4*>(g_words);
    const float4* A4 = reinterpret_cast<const float4*>(g_aggre);
    float4* C4 = reinterpret_cast<float4*>(g_concat);
    float4 x, y;
    if (q < 64) {
        x = W4[(size_t)b * 64 + q];
        y = W4[(size_t)(NB + b) * 64 + q];
    } else {
        int qq = q - 64;
        x = A4[(size_t)b * 64 + qq];
        y = A4[(size_t)(NB + b) * 64 + qq];
    }
    float4 r;
    r.x = x.x + y.x; r.y = x.y + y.y; r.z = x.z + y.z; r.w = x.w + y.w;
    C4[(size_t)b * 128 + q] = r;
}

// ---------------- HMMA fp16 split GEMM with fused softmax stats (R8 version) ----
#define STAGE_BYTES 32768     // A 16KB + B 16KB
#define NSTAGE 3
#define SMEM_DYN (NSTAGE * STAGE_BYTES)
__global__ void __launch_bounds__(256, 2) k_gemm_hmma(float* __restrict__ out) {
    extern __shared__ __align__(128) char smraw[];
    uint32_t sb = cvta_smem(smraw);
    int tid = threadIdx.x, wid = tid >> 5, lane = tid & 31;
    int m0 = blockIdx.x * BM;
    int n0 = blockIdx.y * BN;
    int nt = blockIdx.y;
    int wm = (wid & 3) * 32;
    int wn = (wid >> 2) * 64;
    int g = wid >> 2;                 // n-group 0..1

    const __half* Ag = g_Ah + (size_t)m0 * KPRIME;
    const __half* Bg = g_Bh + (size_t)n0 * KPRIME;

    float c[2][8][4];
    #pragma unroll
    for (int i = 0; i < 2; i++)
        #pragma unroll
        for (int j = 0; j < 8; j++)
            #pragma unroll
            for (int q = 0; q < 4; q++) c[i][j][q] = 0.f;

    auto load_stage = [&](int s, int kc) {
        uint32_t as = sb + s * STAGE_BYTES;
        uint32_t bs = as + 16384;
        const __half* Ak = Ag + kc * BKE;
        const __half* Bk = Bg + kc * BKE;
        #pragma unroll
        for (int i = 0; i < 4; i++) {
            int idx = tid + i * 256;
            int row = idx >> 3, cq = idx & 7;
            cpa16(as + swz((uint32_t)(row * 128 + cq * 16)),
                  Ak + (size_t)row * KPRIME + cq * 8);
        }
        #pragma unroll
        for (int i = 0; i < 4; i++) {
            int idx = tid + i * 256;
            int row = idx >> 3, cq = idx & 7;
            cpa16(bs + swz((uint32_t)(row * 128 + cq * 16)),
                  Bk + (size_t)row * KPRIME + cq * 8);
        }
    };

    load_stage(0, 0); CP_COMMIT();
    load_stage(1, 1); CP_COMMIT();

    int sidx = 0;
    for (int kt = 0; kt < NKIT; kt++) {
        CP_WAIT1();
        __syncthreads();
        if (kt + 2 < NKIT) {
            int ns = sidx + 2; if (ns >= NSTAGE) ns -= NSTAGE;
            load_stage(ns, kt + 2);
        }
        CP_COMMIT();

        uint32_t as = sb + sidx * STAGE_BYTES;
        uint32_t bs = as + 16384;
        #pragma unroll
        for (int kk = 0; kk < 4; kk++) {
            uint32_t afr[2][4], bfr[4][4];
            #pragma unroll
            for (int i = 0; i < 2; i++) {
                int row = wm + i * 16 + (lane & 15);
                int cb = kk * 32 + ((lane >> 4) << 4);
                LDMX4(afr[i], as + swz((uint32_t)(row * 128 + cb)));
            }
            #pragma unroll
            for (int j = 0; j < 4; j++) {
                int row = wn + j * 16 + ((lane >> 4) << 3) + (lane & 7);
                int cb = kk * 32 + (((lane >> 3) & 1) << 4);
                LDMX4(bfr[j], bs + swz((uint32_t)(row * 128 + cb)));
            }
            #pragma unroll
            for (int i = 0; i < 2; i++) {
                #pragma unroll
                for (int j = 0; j < 8; j++) {
                    uint32_t b0 = bfr[j >> 1][(j & 1) * 2];
                    uint32_t b1 = bfr[j >> 1][(j & 1) * 2 + 1];
                    MMA16816(c[i][j], afr[i], b0, b1);
                }
            }
        }
        sidx++; if (sidx >= NSTAGE) sidx = 0;
    }

    // ---- store logits ----
    #pragma unroll
    for (int i = 0; i < 2; i++) {
        int mrow = m0 + wm + i * 16 + (lane >> 2);
        #pragma unroll
        for (int j = 0; j < 8; j++) {
            int n = n0 + wn + j * 8 + (lane & 3) * 2;
            if (n < NV) {
                float2 v0 = make_float2(c[i][j][0], c[i][j][1]);
                float2 v1 = make_float2(c[i][j][2], c[i][j][3]);
                *reinterpret_cast<float2*>(out + (size_t)mrow * NV + n) = v0;
                *reinterpret_cast<float2*>(out + (size_t)(mrow + 8) * NV + n) = v1;
            }
        }
    }

    // ---- fused softmax segment stats (mask n >= NV) ----
    float* rmaxs = reinterpret_cast<float*>(smraw);        // [128][2]
    float* rsums = rmaxs + 256;                            // [128][2]
    float* segm  = rsums + 256;                            // [128]

    const float NEG = -1e30f;
    float lm[2][2];
    #pragma unroll
    for (int i = 0; i < 2; i++)
        #pragma unroll
        for (int h = 0; h < 2; h++) {
            float v = NEG;
            #pragma unroll
            for (int j = 0; j < 8; j++) {
                int n = n0 + wn + j * 8 + (lane & 3) * 2;
                float x0 = (n     < NV) ? c[i][j][2 * h]     : NEG;
                float x1 = (n + 1 < NV) ? c[i][j][2 * h + 1] : NEG;
                v = fmaxf(v, fmaxf(x0, x1));
            }
            v = fmaxf(v, __shfl_xor_sync(0xffffffffu, v, 1));
            v = fmaxf(v, __shfl_xor_sync(0xffffffffu, v, 2));
            lm[i][h] = v;
        }
    if ((lane & 3) == 0) {
        #pragma unroll
        for (int i = 0; i < 2; i++)
            #pragma unroll
            for (int h = 0; h < 2; h++)
                rmaxs[(wm + i * 16 + h * 8 + (lane >> 2)) * 2 + g] = lm[i][h];
    }
    __syncthreads();
    if (tid < 128) {
        segm[tid] = fmaxf(rmaxs[tid * 2], rmaxs[tid * 2 + 1]);
    }
    __syncthreads();

    #pragma unroll
    for (int i = 0; i < 2; i++)
        #pragma unroll
        for (int h = 0; h < 2; h++) {
            float M = segm[wm + i * 16 + h * 8 + (lane >> 2)];
            float s = 0.f;
            #pragma unroll
            for (int j = 0; j < 8; j++) {
                int n = n0 + wn + j * 8 + (lane & 3) * 2;
                if (n     < NV) s += expf(c[i][j][2 * h]     - M);
                if (n + 1 < NV) s += expf(c[i][j][2 * h + 1] - M);
            }
            s += __shfl_xor_sync(0xffffffffu, s, 1);
            s += __shfl_xor_sync(0xffffffffu, s, 2);
            if ((lane & 3) == 0)
                rsums[(wm + i * 16 + h * 8 + (lane >> 2)) * 2 + g] = s;
        }
    __syncthreads();
    if (tid < 128) {
        float s = rsums[tid * 2] + rsums[tid * 2 + 1];
        g_smax[(size_t)nt * NB + m0 + tid] = segm[tid];
        g_ssum[(size_t)nt * NB + m0 + tid] = s;
    }
}

// ---------------- final: merge stats + normalize + exact top-10 -----------------
__global__ void __launch_bounds__(512) k_final(float* __restrict__ logits,
                                               float* __restrict__ out_idx) {
    int b = blockIdx.x, t = threadIdx.x;
    float* row = logits + (size_t)b * NV;
    float4* row4 = reinterpret_cast<float4*>(row);

    __shared__ float sm[512], ss[512];
    {
        float m = (t < NTN) ? g_smax[(size_t)t * NB + b] : -1e30f;
        float s = (t < NTN) ? g_ssum[(size_t)t * NB + b] : 0.f;
        sm[t] = m; ss[t] = s;
        __syncthreads();
        for (int st = 256; st > 0; st >>= 1) {
            if (t < st) {
                float m1 = sm[t], s1 = ss[t];
                float m2 = sm[t + st], s2 = ss[t + st];
                float mm = fmaxf(m1, m2);
                ss[t] = s1 * expf(m1 - mm) + s2 * expf(m2 - mm);
                sm[t] = mm;
            }
            __syncthreads();
        }
    }
    float M = sm[0], S = ss[0];
    float invS = 1.0f / S;
    __syncthreads();

    float tv[NTOPK];
    int ti[NTOPK];
    #pragma unroll
    for (int q = 0; q < NTOPK; q++) { tv[q] = -INFINITY; ti[q] = 0x7fffffff; }

    for (int v4 = t; v4 < NV / 4; v4 += 512) {
        float4 x4 = row4[v4];
        float xs[4] = {x4.x, x4.y, x4.z, x4.w};
        #pragma unroll
        for (int e = 0; e < 4; e++) {
            float x = xs[e];
            if (x > tv[NTOPK - 1]) {
                float nv = x; int ni = v4 * 4 + e;
                #pragma unroll
                for (int q = 0; q < NTOPK; q++) {
                    if (nv > tv[q]) {
                        float fv = tv[q]; tv[q] = nv; nv = fv;
                        int ii = ti[q]; ti[q] = ni; ni = ii;
                    }
                }
            }
        }
        x4.x = expf(x4.x - M) * invS;
        x4.y = expf(x4.y - M) * invS;
        x4.z = expf(x4.z - M) * invS;
        x4.w = expf(x4.w - M) * invS;
        row4[v4] = x4;
    }

    __shared__ float rv[512];
    __shared__ int ri[512];
    for (int r10 = 0; r10 < NTOPK; r10++) {
        rv[t] = tv[0]; ri[t] = ti[0];
        __syncthreads();
        for (int st = 256; st > 0; st >>= 1) {
            if (t < st) {
                float v2 = rv[t + st]; int i2 = ri[t + st];
                if (v2 > rv[t] || (v2 == rv[t] && i2 < ri[t])) { rv[t] = v2; ri[t] = i2; }
            }
            __syncthreads();
        }
        float bv = rv[0]; int bi = ri[0];
        if (t == 0) out_idx[(size_t)b * NTOPK + r10] = (float)bi;
        if (tv[0] == bv && ti[0] == bi) {
            #pragma unroll
            for (int q = 0; q < NTOPK - 1; q++) { tv[q] = tv[q + 1]; ti[q] = ti[q + 1]; }
            tv[NTOPK - 1] = -INFINITY; ti[NTOPK - 1] = 0x7fffffff;
        }
        __syncthreads();
    }
}

// ---------------- host launcher --------------------------------------------------
extern "C" void kernel_launch(void* const* d_in, const int* in_sizes, int n_in,
                              void* d_out, int out_size) {
    const int*   wl_ids = (const int*)  d_in[0];
    const int*   wr_ids = (const int*)  d_in[1];
    const int*   cl_ids = (const int*)  d_in[2];
    const int*   cr_ids = (const int*)  d_in[3];
    const float* wemb   = (const float*)d_in[4];
    const float* cemb   = (const float*)d_in[5];
    const float* W_a    = (const float*)d_in[6];
    const float* b_a    = (const float*)d_in[7];
    const float* W_c    = (const float*)d_in[8];
    const float* b_c    = (const float*)d_in[9];
    float* out = (float*)d_out;

    cudaFuncSetAttribute(k_gemm_hmma,
                         cudaFuncAttributeMaxDynamicSharedMemorySize, SMEM_DYN);

    float* g_words_p;  cudaGetSymbolAddress((void**)&g_words_p,  g_words);
    float* g_align_p;  cudaGetSymbolAddress((void**)&g_align_p,  g_align);
    float* g_concat_p; cudaGetSymbolAddress((void**)&g_concat_p, g_concat);

    // 0: fused gather + B' conversion
    k_prep<<<25512, 256>>>(wl_ids, wr_ids, wemb, cemb);
    // 1: align GEMM (2048x256, K=256) — 256 CTAs, pipelined
    k_gemm_small<0><<<dim3(4, 64), 128>>>(g_words_p, W_a, b_a, g_align_p,
                                          2048, ND, ND);
    // 2: attention
    k_attend<<<dim3(NB, 2), 256>>>(cl_ids, cr_ids, cemb);
    // 3: concat
    k_concat<<<512, 256>>>();
    // 4: phrase GEMM with fused A' split epilogue (1024x256, K=512) — 128 CTAs
    k_gemm_small<1><<<dim3(4, 32), 128>>>(g_concat_p, W_c, b_c, nullptr,
                                          NB, ND, 2 * ND);
    // 5: tensor-core GEMM with fused stats
    k_gemm_hmma<<<dim3(8, NTN), 256, SMEM_DYN>>>(out);
    // 6: merge + normalize + top-10
    k_final<<<NB, 512>>>(out, out + (size_t)NB * NV);
}